// round 11
// baseline (speedup 1.0000x reference)
#include <cuda_runtime.h>
#include <cuda_fp16.h>

#define NN 20000
#define EE 100000
#define FN 26
#define FE 21
#define H1C 64
#define H2C 30
#define NCHUNK 148
#define WARM 32
#define CLEN 136   // 148*136 = 20128 >= 20000, divisible by 4

// ---------------- device scratch ----------------
__device__ float  g_W1t[22 * 26 * 64];        // [f][i][o]  (f=21 -> eb1 row)
__device__ float  g_W2t[22 * 64 * 32];        // [f][i][o pad32]
__device__ __half g_P1h[NN * 1408];           // fp16 per-node contraction, layer 1
__device__ __half g_P2h[NN * 704 + 128];      // +pad
__device__ float  g_acc1[NN * 64];
__device__ float  g_acc2[NN * 32];
__device__ int    g_cnt[NN];                  // dst degree
__device__ int    g_scnt[NN];                 // src degree (for sort)
__device__ int    g_scur[NN];                 // scatter cursor
__device__ int    g_sid[EE];                  // sorted -> original edge id
__device__ int    g_ssrc[EE];
__device__ int    g_sdst[EE];
__device__ float  g_h1[NN * 64];
__device__ float  g_pre[2 * NN * 256];        // [dir][t][gate-row]
__device__ float  g_hcat[NN * 128];

// ---------------- helpers ----------------
__device__ __forceinline__ unsigned long long pk2(float lo, float hi) {
    unsigned long long r;
    asm("mov.b64 %0,{%1,%2};" : "=l"(r) : "f"(lo), "f"(hi));
    return r;
}
__device__ __forceinline__ void upk2(unsigned long long v, float& lo, float& hi) {
    asm("mov.b64 {%0,%1},%2;" : "=f"(lo), "=f"(hi) : "l"(v));
}
__device__ __forceinline__ unsigned long long fma2(unsigned long long a, unsigned long long b,
                                                   unsigned long long c) {
    unsigned long long d;
    asm("fma.rn.f32x2 %0,%1,%2,%3;" : "=l"(d) : "l"(a), "l"(b), "l"(c));
    return d;
}
__device__ __forceinline__ float fast_tanh(float x) {
    return __fdividef(2.f, 1.f + __expf(-2.f * x)) - 1.f;
}

// ---------------- init: zero + weight rearrange ----------------
__global__ void k_init(const float* __restrict__ ew1, const float* __restrict__ eb1,
                       const float* __restrict__ ew2, const float* __restrict__ eb2) {
    int i = blockIdx.x * blockDim.x + threadIdx.x;
    int st = gridDim.x * blockDim.x;
    for (int j = i; j < NN * 64; j += st) g_acc1[j] = 0.f;
    for (int j = i; j < NN * 32; j += st) g_acc2[j] = 0.f;
    for (int j = i; j < NN; j += st) { g_cnt[j] = 0; g_scnt[j] = 0; }
    for (int idx = i; idx < 22 * 26 * 64; idx += st) {
        int f = idx / 1664, r = idx - f * 1664;
        int ii = r >> 6, o = r & 63;
        g_W1t[idx] = (f < 21) ? ew1[(ii * 64 + o) * 21 + f] : eb1[ii * 64 + o];
    }
    for (int idx = i; idx < 22 * 64 * 32; idx += st) {
        int f = idx / 2048, r = idx - f * 2048;
        int ii = r >> 5, o = r & 31;
        float v = 0.f;
        if (o < 30) v = (f < 21) ? ew2[(ii * 30 + o) * 21 + f] : eb2[ii * 30 + o];
        g_W2t[idx] = v;
    }
}

// ---------------- hist: src + dst degree ----------------
__global__ void k_hist(const int* __restrict__ ei) {
    int e = blockIdx.x * blockDim.x + threadIdx.x;
    if (e < EE) {
        atomicAdd(&g_scnt[ei[e]], 1);
        atomicAdd(&g_cnt[ei[EE + e]], 1);
    }
}

// ---------------- scan: exclusive prefix of src counts (1 block) ----------------
__global__ void __launch_bounds__(512) k_scan() {
    __shared__ int wsum[16];
    int t = threadIdx.x;
    int base = t * 40;
    int loc[40];
    int s = 0;
#pragma unroll
    for (int j = 0; j < 40; j++) {
        int b = base + j;
        int v = (b < NN) ? g_scnt[b] : 0;
        loc[j] = s;
        s += v;
    }
    int lane = t & 31, wid = t >> 5;
    int inc = s;
#pragma unroll
    for (int d = 1; d < 32; d <<= 1) {
        int o = __shfl_up_sync(0xffffffffu, inc, d);
        if (lane >= d) inc += o;
    }
    if (lane == 31) wsum[wid] = inc;
    __syncthreads();
    if (wid == 0) {
        int v = (lane < 16) ? wsum[lane] : 0;
#pragma unroll
        for (int d = 1; d < 16; d <<= 1) {
            int o = __shfl_up_sync(0xffffffffu, v, d);
            if (lane >= d) v += o;
        }
        if (lane < 16) wsum[lane] = v;   // inclusive warp sums
    }
    __syncthreads();
    int warpoff = (wid > 0) ? wsum[wid - 1] : 0;
    int excl = warpoff + inc - s;
#pragma unroll
    for (int j = 0; j < 40; j++) {
        int b = base + j;
        if (b < NN) g_scur[b] = excl + loc[j];
    }
}

// ---------------- scatter: edges sorted by src ----------------
__global__ void k_scatter(const int* __restrict__ ei) {
    int e = blockIdx.x * blockDim.x + threadIdx.x;
    if (e >= EE) return;
    int s = ei[e];
    int pos = atomicAdd(&g_scur[s], 1);
    g_sid[pos] = e;
    g_ssrc[pos] = s;
    g_sdst[pos] = ei[EE + e];
}

// ---------------- P1: node contraction layer 1 (smem weights, 16-node batch) ----------------
__global__ void __launch_bounds__(352, 1) k_p1(const float* __restrict__ x) {
    extern __shared__ float sW[];           // 22*26*64 floats = 146.4 KB
    __shared__ float xs[16][FN];
    for (int i = threadIdx.x; i < 22 * 26 * 64; i += 352) sW[i] = g_W1t[i];
    int u = threadIdx.x;                    // 352 = 22 f-rows * 16 quads
    int f = u >> 4, q = u & 15;
    const unsigned long long* wp =
        (const unsigned long long*)sW + ((f * 1664 + q * 4) >> 1);
    __syncthreads();
    for (int n0 = blockIdx.x * 16; n0 < NN; n0 += gridDim.x * 16) {
        for (int idx = u; idx < 16 * FN; idx += 352)
            xs[idx / FN][idx % FN] = x[(n0 + idx / FN) * FN + (idx % FN)];
        __syncthreads();
        unsigned long long acc[16][2] = {};
#pragma unroll
        for (int i = 0; i < FN; i++) {
            unsigned long long w0 = wp[i * 32], w1 = wp[i * 32 + 1];
#pragma unroll
            for (int b = 0; b < 16; b++) {
                float xv = xs[b][i];
                unsigned long long xb = pk2(xv, xv);
                acc[b][0] = fma2(w0, xb, acc[b][0]);
                acc[b][1] = fma2(w1, xb, acc[b][1]);
            }
        }
#pragma unroll
        for (int b = 0; b < 16; b++) {
            float a0, a1, a2, a3;
            upk2(acc[b][0], a0, a1);
            upk2(acc[b][1], a2, a3);
            __half2* dst = (__half2*)(g_P1h + (n0 + b) * 1408 + f * 64 + q * 4);
            dst[0] = __floats2half2_rn(a0, a1);
            dst[1] = __floats2half2_rn(a2, a3);
        }
        __syncthreads();
    }
}

// ---------------- edge 1: sorted edges, one per warp ----------------
__global__ void k_edge1(const float* __restrict__ ea) {
    int gt = blockIdx.x * blockDim.x + threadIdx.x;
    int es = gt >> 5, lane = gt & 31;
    if (es >= EE) return;
    int src = g_ssrc[es], dst = g_sdst[es], eid = g_sid[es];
    const __half* P = g_P1h + src * 1408;
    int half_sel = lane >> 4;
    int col4 = (lane & 15) * 4;
    float myev = (lane < FE) ? __ldg(ea + eid * FE + lane) : 1.0f;
    float a0 = 0.f, a1 = 0.f, a2 = 0.f, a3 = 0.f;
#pragma unroll
    for (int p = 0; p < 11; p++) {
        int row = 2 * p + half_sel;    // 0..21 (21 = bias row)
        uint2 v = *(const uint2*)(P + row * 64 + col4);
        float c = __shfl_sync(0xffffffffu, myev, row);
        float2 f01 = __half22float2(*(__half2*)&v.x);
        float2 f23 = __half22float2(*(__half2*)&v.y);
        a0 += c * f01.x; a1 += c * f01.y;
        a2 += c * f23.x; a3 += c * f23.y;
    }
    a0 += __shfl_xor_sync(0xffffffffu, a0, 16);
    a1 += __shfl_xor_sync(0xffffffffu, a1, 16);
    a2 += __shfl_xor_sync(0xffffffffu, a2, 16);
    a3 += __shfl_xor_sync(0xffffffffu, a3, 16);
    float* dp = g_acc1 + dst * 64 + col4;
    if (half_sel == 0) {
        atomicAdd(dp, a0);
        atomicAdd(dp + 1, a1);
    } else {
        atomicAdd(dp + 2, a2);
        atomicAdd(dp + 3, a3);
    }
}

// ---------------- fused node1 + P2 (32-node tiles) ----------------
__global__ void __launch_bounds__(352, 1) k_p2n1(const float* __restrict__ x,
                                                 const float* __restrict__ root1,
                                                 const float* __restrict__ b1,
                                                 const float* __restrict__ g1,
                                                 const float* __restrict__ be1) {
    extern __shared__ float sW[];           // 22*64*32 floats = 180 KB
    __shared__ float rs[FN * 64];
    __shared__ float hs[32][H1C];
    for (int i = threadIdx.x; i < 22 * 64 * 32; i += 352) sW[i] = g_W2t[i];
    for (int i = threadIdx.x; i < FN * 64; i += 352) rs[i] = root1[i];
    int tid = threadIdx.x;
    int wwarp = tid >> 5, lane = tid & 31;
    int which = tid >= 176;
    int u = tid - which * 176;              // 176 = 22 f-rows * 8 quads
    int f = u >> 3, q = u & 7;
    const unsigned long long* wp =
        (const unsigned long long*)sW + ((f * 2048 + q * 4) >> 1);
    __syncthreads();
    for (int n0 = blockIdx.x * 32; n0 < NN; n0 += gridDim.x * 32) {
        // ---- node1 phase: warp per node ----
        for (int r = wwarp; r < 32; r += 11) {
            int n = n0 + r;
            int cnt = g_cnt[n];
            float inv = 1.f / (float)(cnt > 0 ? cnt : 1);
            int o0 = lane * 2;
            float v0 = g_acc1[n * 64 + o0] * inv;
            float v1 = g_acc1[n * 64 + o0 + 1] * inv;
#pragma unroll
            for (int i = 0; i < FN; i++) {
                float xv = __ldg(x + n * FN + i);
                v0 += xv * rs[i * 64 + o0];
                v1 += xv * rs[i * 64 + o0 + 1];
            }
            v0 += b1[o0];
            v1 += b1[o0 + 1];
            float s = v0 + v1, sq = v0 * v0 + v1 * v1;
#pragma unroll
            for (int d = 16; d > 0; d >>= 1) {
                s += __shfl_xor_sync(0xffffffffu, s, d);
                sq += __shfl_xor_sync(0xffffffffu, sq, d);
            }
            float m = s * (1.f / 64.f);
            float var = fmaxf(sq * (1.f / 64.f) - m * m, 0.f);
            float rr = rsqrtf(var + 1e-5f);
            float y0 = (v0 - m) * rr * g1[o0] + be1[o0];
            float y1 = (v1 - m) * rr * g1[o0 + 1] + be1[o0 + 1];
            y0 = y0 > 0.f ? y0 : 0.01f * y0;
            y1 = y1 > 0.f ? y1 : 0.01f * y1;
            hs[r][o0] = y0;
            hs[r][o0 + 1] = y1;
            g_h1[n * 64 + o0] = y0;
            g_h1[n * 64 + o0 + 1] = y1;
        }
        __syncthreads();
        // ---- P2 phase ----
        unsigned long long acc[16][2] = {};
#pragma unroll
        for (int i = 0; i < H1C; i++) {
            unsigned long long w0 = wp[i * 16], w1 = wp[i * 16 + 1];
#pragma unroll
            for (int b = 0; b < 16; b++) {
                float hv = hs[which * 16 + b][i];
                unsigned long long hb = pk2(hv, hv);
                acc[b][0] = fma2(w0, hb, acc[b][0]);
                acc[b][1] = fma2(w1, hb, acc[b][1]);
            }
        }
#pragma unroll
        for (int b = 0; b < 16; b++) {
            float a0, a1, a2, a3;
            upk2(acc[b][0], a0, a1);
            upk2(acc[b][1], a2, a3);
            __half2* dst2 =
                (__half2*)(g_P2h + (n0 + which * 16 + b) * 704 + f * 32 + q * 4);
            dst2[0] = __floats2half2_rn(a0, a1);
            dst2[1] = __floats2half2_rn(a2, a3);
        }
        __syncthreads();
    }
}

// ---------------- edge 2: sorted edges, one per warp ----------------
__global__ void k_edge2(const float* __restrict__ ea) {
    int gt = blockIdx.x * blockDim.x + threadIdx.x;
    int es = gt >> 5, lane = gt & 31;
    if (es >= EE) return;
    int src = g_ssrc[es], dst = g_sdst[es], eid = g_sid[es];
    const __half* P = g_P2h + src * 704;
    int quad = lane >> 3;
    int col4 = (lane & 7) * 4;
    float myev = (lane < FE) ? __ldg(ea + eid * FE + lane) : (lane == 21 ? 1.0f : 0.0f);
    float a0 = 0.f, a1 = 0.f, a2 = 0.f, a3 = 0.f;
#pragma unroll
    for (int qq = 0; qq < 6; qq++) {
        int row = 4 * qq + quad;       // 0..23 (21 bias, 22/23 pad-zero)
        uint2 v = *(const uint2*)(P + row * 32 + col4);
        float c = __shfl_sync(0xffffffffu, myev, row);
        float2 f01 = __half22float2(*(__half2*)&v.x);
        float2 f23 = __half22float2(*(__half2*)&v.y);
        a0 += c * f01.x; a1 += c * f01.y;
        a2 += c * f23.x; a3 += c * f23.y;
    }
#pragma unroll
    for (int d = 8; d <= 16; d <<= 1) {
        a0 += __shfl_xor_sync(0xffffffffu, a0, d);
        a1 += __shfl_xor_sync(0xffffffffu, a1, d);
        a2 += __shfl_xor_sync(0xffffffffu, a2, d);
        a3 += __shfl_xor_sync(0xffffffffu, a3, d);
    }
    float val = (quad == 0) ? a0 : (quad == 1) ? a1 : (quad == 2) ? a2 : a3;
    atomicAdd(g_acc2 + dst * 32 + col4 + quad, val);
}

// ---------------- fused node2 + LSTM input projections ----------------
__global__ void __launch_bounds__(256) k_n2pre(const float* __restrict__ root2,
                                               const float* __restrict__ b2,
                                               const float* __restrict__ g2,
                                               const float* __restrict__ be2,
                                               const float* __restrict__ Wf,
                                               const float* __restrict__ bihf,
                                               const float* __restrict__ bhhf,
                                               const float* __restrict__ Wb,
                                               const float* __restrict__ bihb,
                                               const float* __restrict__ bhhb) {
    __shared__ float rs[H1C * H2C];
    __shared__ float hsm[32][H2C];
    for (int i = threadIdx.x; i < H1C * H2C; i += 256) rs[i] = root2[i];
    __syncthreads();
    int nb = blockIdx.x * 32;
    int w = threadIdx.x >> 5, lane = threadIdx.x & 31;
    // ---- node2 phase: warp per node ----
    for (int r = w; r < 32; r += 8) {
        int n = nb + r;
        float v = 0.f;
        if (lane < 30) {
            int cnt = g_cnt[n];
            v = g_acc2[n * 32 + lane] * (1.f / (float)(cnt > 0 ? cnt : 1));
#pragma unroll
            for (int i = 0; i < H1C; i++) v += g_h1[n * 64 + i] * rs[i * 30 + lane];
            v += b2[lane];
        }
        float s = (lane < 30) ? v : 0.f;
        float sq = (lane < 30) ? v * v : 0.f;
#pragma unroll
        for (int d = 16; d > 0; d >>= 1) {
            s += __shfl_xor_sync(0xffffffffu, s, d);
            sq += __shfl_xor_sync(0xffffffffu, sq, d);
        }
        float m = s * (1.f / 30.f);
        float var = fmaxf(sq * (1.f / 30.f) - m * m, 0.f);
        float rr = rsqrtf(var + 1e-5f);
        if (lane < 30) {
            float y = (v - m) * rr * g2[lane] + be2[lane];
            hsm[r][lane] = y > 0.f ? y : 0.01f * y;
        }
    }
    __syncthreads();
    // ---- pre phase ----
    int g = threadIdx.x;
    float wr[H2C];
#pragma unroll
    for (int k = 0; k < H2C; k++) wr[k] = __ldg(Wf + g * H2C + k);
    float bias = bihf[g] + bhhf[g];
    for (int nn = 0; nn < 32; nn++) {
        float a = bias;
#pragma unroll
        for (int k = 0; k < H2C; k++) a += wr[k] * hsm[nn][k];
        g_pre[(nb + nn) * 256 + g] = a;
    }
#pragma unroll
    for (int k = 0; k < H2C; k++) wr[k] = __ldg(Wb + g * H2C + k);
    bias = bihb[g] + bhhb[g];
    for (int nn = 0; nn < 32; nn++) {
        float a = bias;
#pragma unroll
        for (int k = 0; k < H2C; k++) a += wr[k] * hsm[nn][k];
        g_pre[NN * 256 + (NN - 1 - (nb + nn)) * 256 + g] = a;
    }
}

// ---------------- chunked BiLSTM: 1 barrier/step, warp-local gate combine ----------------
__global__ void __launch_bounds__(256, 2) k_lstm(const float* __restrict__ WhhF,
                                                 const float* __restrict__ WhhB) {
    int chunk = blockIdx.x >> 1;
    int dir = blockIdx.x & 1;
    const float* Whh = dir ? WhhB : WhhF;
    const float* pre = g_pre + (dir ? NN * 256 : 0);
    int tid = threadIdx.x;
    int w = tid >> 5, lane = tid & 31;
    int type = lane >> 3;          // 0=i 1=f 2=g 3=o
    int ci = lane & 7;
    int cell = w * 8 + ci;
    int row = type * 64 + cell;    // PyTorch gate-row order
    unsigned long long wp[32];
#pragma unroll
    for (int k = 0; k < 32; k++)
        wp[k] = pk2(__ldg(Whh + row * 64 + 2 * k), __ldg(Whh + row * 64 + 2 * k + 1));
    __shared__ __align__(16) float sh_h[2][64];
    int tstart = chunk * CLEN;
    int tend = tstart + CLEN;
    if (tend > NN) tend = NN;
    int t0 = tstart - WARM;
    if (t0 < 0) t0 = 0;
    float c = 0.f;
    if (tid < 64) {
        sh_h[0][tid] = 0.f;
        sh_h[1][tid] = 0.f;
    }
    __syncthreads();
    float preR[4];
#pragma unroll
    for (int u2 = 0; u2 < 4; u2++)
        preR[u2] = (t0 + u2 < tend) ? __ldg(pre + (t0 + u2) * 256 + row) : 0.f;
    for (int tb = t0; tb < tend; tb += 4) {
#pragma unroll
        for (int u2 = 0; u2 < 4; u2++) {
            int t = tb + u2;
            if (t < tend) {   // uniform across block
                int rb = u2 & 1;
                float accs = preR[u2];
                int tp = t + 4;
                preR[u2] = (tp < tend) ? __ldg(pre + tp * 256 + row) : 0.f;
                unsigned long long a0 = pk2(accs, 0.f), a1 = 0ull, a2 = 0ull, a3 = 0ull;
                const ulonglong2* hp = (const ulonglong2*)sh_h[rb];
#pragma unroll
                for (int kk = 0; kk < 16; kk++) {
                    ulonglong2 hv = hp[kk];
                    if ((kk & 1) == 0) {
                        a0 = fma2(wp[2 * kk], hv.x, a0);
                        a1 = fma2(wp[2 * kk + 1], hv.y, a1);
                    } else {
                        a2 = fma2(wp[2 * kk], hv.x, a2);
                        a3 = fma2(wp[2 * kk + 1], hv.y, a3);
                    }
                }
                float l0, u0, l1, u1, l2, u2f, l3, u3;
                upk2(a0, l0, u0); upk2(a1, l1, u1);
                upk2(a2, l2, u2f); upk2(a3, l3, u3);
                float xg = ((l0 + l1) + (l2 + l3)) + ((u0 + u1) + (u2f + u3));
                float z = (type == 2) ? xg : 0.5f * xg;
                float th = fast_tanh(z);
                float av = (type == 2) ? th : 0.5f * th + 0.5f;
                float fv = __shfl_sync(0xffffffffu, av, (lane + 8) & 31);
                float gv = __shfl_sync(0xffffffffu, av, (lane + 16) & 31);
                float ov = __shfl_sync(0xffffffffu, av, (lane + 24) & 31);
                if (type == 0) {
                    c = fv * c + av * gv;
                    float hv = ov * fast_tanh(c);
                    sh_h[1 - rb][cell] = hv;
                    if (t >= tstart) {
                        int node = dir ? (NN - 1 - t) : t;
                        g_hcat[node * 128 + dir * 64 + cell] = hv;
                    }
                }
                __syncthreads();
            }
        }
    }
}

// ---------------- final LN + FC ----------------
__global__ void k_final(const float* __restrict__ gl, const float* __restrict__ bl,
                        const float* __restrict__ fcw, const float* __restrict__ fcb,
                        float* __restrict__ out) {
    int n = (blockIdx.x * blockDim.x + threadIdx.x) >> 5;
    int lane = threadIdx.x & 31;
    if (n >= NN) return;
    float4 v = *(const float4*)(g_hcat + n * 128 + lane * 4);
    float s = v.x + v.y + v.z + v.w;
    float sq = v.x * v.x + v.y * v.y + v.z * v.z + v.w * v.w;
#pragma unroll
    for (int d = 16; d > 0; d >>= 1) {
        s += __shfl_xor_sync(0xffffffffu, s, d);
        sq += __shfl_xor_sync(0xffffffffu, sq, d);
    }
    float m = s * (1.f / 128.f);
    float var = fmaxf(sq * (1.f / 128.f) - m * m, 0.f);
    float r = rsqrtf(var + 1e-5f);
    float o0 = 0.f, o1 = 0.f;
    int i0 = lane * 4;
    float vv[4] = {v.x, v.y, v.z, v.w};
#pragma unroll
    for (int q = 0; q < 4; q++) {
        float y = (vv[q] - m) * r * __ldg(gl + i0 + q) + __ldg(bl + i0 + q);
        o0 += y * __ldg(fcw + i0 + q);
        o1 += y * __ldg(fcw + 128 + i0 + q);
    }
#pragma unroll
    for (int d = 16; d > 0; d >>= 1) {
        o0 += __shfl_xor_sync(0xffffffffu, o0, d);
        o1 += __shfl_xor_sync(0xffffffffu, o1, d);
    }
    if (lane == 0) {
        out[n * 2] = o0 + fcb[0];
        out[n * 2 + 1] = o1 + fcb[1];
    }
}

// ---------------- launcher ----------------
extern "C" void kernel_launch(void* const* d_in, const int* in_sizes, int n_in,
                              void* d_out, int out_size) {
    const float* x    = (const float*)d_in[0];
    const int*   ei   = (const int*)d_in[1];
    const float* ea   = (const float*)d_in[2];
    const float* ew1  = (const float*)d_in[3];
    const float* eb1  = (const float*)d_in[4];
    const float* root1= (const float*)d_in[5];
    const float* b1   = (const float*)d_in[6];
    const float* g1   = (const float*)d_in[7];
    const float* be1  = (const float*)d_in[8];
    const float* ew2  = (const float*)d_in[9];
    const float* eb2  = (const float*)d_in[10];
    const float* root2= (const float*)d_in[11];
    const float* b2   = (const float*)d_in[12];
    const float* g2   = (const float*)d_in[13];
    const float* be2  = (const float*)d_in[14];
    const float* Wih_f= (const float*)d_in[15];
    const float* Whh_f= (const float*)d_in[16];
    const float* bih_f= (const float*)d_in[17];
    const float* bhh_f= (const float*)d_in[18];
    const float* Wih_b= (const float*)d_in[19];
    const float* Whh_b= (const float*)d_in[20];
    const float* bih_b= (const float*)d_in[21];
    const float* bhh_b= (const float*)d_in[22];
    const float* gl   = (const float*)d_in[23];
    const float* bl   = (const float*)d_in[24];
    const float* fcw  = (const float*)d_in[25];
    const float* fcb  = (const float*)d_in[26];
    float* out = (float*)d_out;

    static bool attr_done = false;
    if (!attr_done) {
        cudaFuncSetAttribute(k_p1, cudaFuncAttributeMaxDynamicSharedMemorySize,
                             22 * 26 * 64 * 4);
        cudaFuncSetAttribute(k_p2n1, cudaFuncAttributeMaxDynamicSharedMemorySize,
                             22 * 64 * 32 * 4);
        attr_done = true;
    }

    k_init<<<256, 256>>>(ew1, eb1, ew2, eb2);
    k_hist<<<(EE + 255) / 256, 256>>>(ei);
    k_scan<<<1, 512>>>();
    k_scatter<<<(EE + 255) / 256, 256>>>(ei);
    k_p1<<<148, 352, 22 * 26 * 64 * 4>>>(x);
    k_edge1<<<(EE * 32 + 255) / 256, 256>>>(ea);
    k_p2n1<<<148, 352, 22 * 64 * 32 * 4>>>(x, root1, b1, g1, be1);
    k_edge2<<<(EE * 32 + 255) / 256, 256>>>(ea);
    k_n2pre<<<NN / 32, 256>>>(root2, b2, g2, be2,
                              Wih_f, bih_f, bhh_f, Wih_b, bih_b, bhh_b);
    k_lstm<<<2 * NCHUNK, 256>>>(Whh_f, Whh_b);
    k_final<<<(NN * 32 + 255) / 256, 256>>>(gl, bl, fcw, fcb, out);
}

// round 15
// speedup vs baseline: 1.0341x; 1.0341x over previous
#include <cuda_runtime.h>
#include <cuda_fp16.h>

#define NN 20000
#define EE 100000
#define FN 26
#define FE 21
#define H1C 64
#define H2C 30
#define NCHUNK 148
#define WARM 32
#define CLEN 136   // 148*136 = 20128 >= 20000, divisible by 4

// ---------------- device scratch ----------------
__device__ float  g_W1t[22 * 26 * 64];        // [f][i][o]  (f=21 -> eb1 row)
__device__ float  g_W2t[22 * 64 * 32];        // [f][i][o pad32]
__device__ __half g_P1h[NN * 1408];           // fp16 per-node contraction, layer 1
__device__ __half g_P2h[NN * 704 + 128];      // +pad
__device__ float  g_acc1[NN * 64];
__device__ float  g_acc2[NN * 32];
__device__ int    g_cnt[NN];                  // dst degree
__device__ float  g_h1[NN * 64];
__device__ float  g_pre[2 * NN * 256];        // [dir][t][gate-row]
__device__ float  g_hcat[NN * 128];

// ---------------- helpers ----------------
__device__ __forceinline__ unsigned long long pk2(float lo, float hi) {
    unsigned long long r;
    asm("mov.b64 %0,{%1,%2};" : "=l"(r) : "f"(lo), "f"(hi));
    return r;
}
__device__ __forceinline__ void upk2(unsigned long long v, float& lo, float& hi) {
    asm("mov.b64 {%0,%1},%2;" : "=f"(lo), "=f"(hi) : "l"(v));
}
__device__ __forceinline__ unsigned long long fma2(unsigned long long a, unsigned long long b,
                                                   unsigned long long c) {
    unsigned long long d;
    asm("fma.rn.f32x2 %0,%1,%2,%3;" : "=l"(d) : "l"(a), "l"(b), "l"(c));
    return d;
}
__device__ __forceinline__ float fast_tanh(float x) {
    return __fdividef(2.f, 1.f + __expf(-2.f * x)) - 1.f;
}

// ---------------- init: zero + weight rearrange ----------------
__global__ void k_init(const float* __restrict__ ew1, const float* __restrict__ eb1,
                       const float* __restrict__ ew2, const float* __restrict__ eb2) {
    int i = blockIdx.x * blockDim.x + threadIdx.x;
    int st = gridDim.x * blockDim.x;
    for (int j = i; j < NN * 64; j += st) g_acc1[j] = 0.f;
    for (int j = i; j < NN * 32; j += st) g_acc2[j] = 0.f;
    for (int j = i; j < NN; j += st) g_cnt[j] = 0;
    for (int idx = i; idx < 22 * 26 * 64; idx += st) {
        int f = idx / 1664, r = idx - f * 1664;
        int ii = r >> 6, o = r & 63;
        g_W1t[idx] = (f < 21) ? ew1[(ii * 64 + o) * 21 + f] : eb1[ii * 64 + o];
    }
    for (int idx = i; idx < 22 * 64 * 32; idx += st) {
        int f = idx / 2048, r = idx - f * 2048;
        int ii = r >> 5, o = r & 31;
        float v = 0.f;
        if (o < 30) v = (f < 21) ? ew2[(ii * 30 + o) * 21 + f] : eb2[ii * 30 + o];
        g_W2t[idx] = v;
    }
}

__global__ void k_cnt(const int* __restrict__ ei) {
    int e = blockIdx.x * blockDim.x + threadIdx.x;
    if (e < EE) atomicAdd(&g_cnt[ei[EE + e]], 1);
}

// ---------------- P1: node contraction layer 1 (smem weights, 16-node batch) ----------------
__global__ void __launch_bounds__(352, 1) k_p1(const float* __restrict__ x) {
    extern __shared__ float sW[];           // 22*26*64 floats = 146.4 KB
    __shared__ float xs[16][FN];
    for (int i = threadIdx.x; i < 22 * 26 * 64; i += 352) sW[i] = g_W1t[i];
    int u = threadIdx.x;                    // 352 = 22 f-rows * 16 quads
    int f = u >> 4, q = u & 15;
    const unsigned long long* wp =
        (const unsigned long long*)sW + ((f * 1664 + q * 4) >> 1);
    __syncthreads();
    for (int n0 = blockIdx.x * 16; n0 < NN; n0 += gridDim.x * 16) {
        for (int idx = u; idx < 16 * FN; idx += 352)
            xs[idx / FN][idx % FN] = x[(n0 + idx / FN) * FN + (idx % FN)];
        __syncthreads();
        unsigned long long acc[16][2] = {};
#pragma unroll
        for (int i = 0; i < FN; i++) {
            unsigned long long w0 = wp[i * 32], w1 = wp[i * 32 + 1];
#pragma unroll
            for (int b = 0; b < 16; b++) {
                float xv = xs[b][i];
                unsigned long long xb = pk2(xv, xv);
                acc[b][0] = fma2(w0, xb, acc[b][0]);
                acc[b][1] = fma2(w1, xb, acc[b][1]);
            }
        }
#pragma unroll
        for (int b = 0; b < 16; b++) {
            float a0, a1, a2, a3;
            upk2(acc[b][0], a0, a1);
            upk2(acc[b][1], a2, a3);
            __half2* dst = (__half2*)(g_P1h + (n0 + b) * 1408 + f * 64 + q * 4);
            dst[0] = __floats2half2_rn(a0, a1);
            dst[1] = __floats2half2_rn(a2, a3);
        }
        __syncthreads();
    }
}

// ---------------- edge 1: one edge per warp, coop coeff load + shfl ----------------
__global__ void k_edge1(const int* __restrict__ ei, const float* __restrict__ ea) {
    int gt = blockIdx.x * blockDim.x + threadIdx.x;
    int e = gt >> 5, lane = gt & 31;
    if (e >= EE) return;
    int src = ei[e], dst = ei[EE + e];
    const __half* P = g_P1h + src * 1408;
    int half_sel = lane >> 4;
    int col4 = (lane & 15) * 4;
    float myev = (lane < FE) ? __ldg(ea + e * FE + lane) : 1.0f;
    float a0 = 0.f, a1 = 0.f, a2 = 0.f, a3 = 0.f;
#pragma unroll
    for (int p = 0; p < 11; p++) {
        int row = 2 * p + half_sel;    // 0..21 (21 = bias row)
        uint2 v = *(const uint2*)(P + row * 64 + col4);
        float c = __shfl_sync(0xffffffffu, myev, row);
        float2 f01 = __half22float2(*(__half2*)&v.x);
        float2 f23 = __half22float2(*(__half2*)&v.y);
        a0 += c * f01.x; a1 += c * f01.y;
        a2 += c * f23.x; a3 += c * f23.y;
    }
    a0 += __shfl_xor_sync(0xffffffffu, a0, 16);
    a1 += __shfl_xor_sync(0xffffffffu, a1, 16);
    a2 += __shfl_xor_sync(0xffffffffu, a2, 16);
    a3 += __shfl_xor_sync(0xffffffffu, a3, 16);
    float* dp = g_acc1 + dst * 64 + col4;
    if (half_sel == 0) {
        atomicAdd(dp, a0);
        atomicAdd(dp + 1, a1);
    } else {
        atomicAdd(dp + 2, a2);
        atomicAdd(dp + 3, a3);
    }
}

// ---------------- fused node1 + P2 (32-node tiles) ----------------
__global__ void __launch_bounds__(352, 1) k_p2n1(const float* __restrict__ x,
                                                 const float* __restrict__ root1,
                                                 const float* __restrict__ b1,
                                                 const float* __restrict__ g1,
                                                 const float* __restrict__ be1) {
    extern __shared__ float sW[];           // 22*64*32 floats = 180 KB
    __shared__ float rs[FN * 64];
    __shared__ float hs[32][H1C];
    for (int i = threadIdx.x; i < 22 * 64 * 32; i += 352) sW[i] = g_W2t[i];
    for (int i = threadIdx.x; i < FN * 64; i += 352) rs[i] = root1[i];
    int tid = threadIdx.x;
    int wwarp = tid >> 5, lane = tid & 31;
    int which = tid >= 176;
    int u = tid - which * 176;              // 176 = 22 f-rows * 8 quads
    int f = u >> 3, q = u & 7;
    const unsigned long long* wp =
        (const unsigned long long*)sW + ((f * 2048 + q * 4) >> 1);
    __syncthreads();
    for (int n0 = blockIdx.x * 32; n0 < NN; n0 += gridDim.x * 32) {
        // ---- node1 phase: warp per node ----
        for (int r = wwarp; r < 32; r += 11) {
            int n = n0 + r;
            int cnt = g_cnt[n];
            float inv = 1.f / (float)(cnt > 0 ? cnt : 1);
            int o0 = lane * 2;
            float v0 = g_acc1[n * 64 + o0] * inv;
            float v1 = g_acc1[n * 64 + o0 + 1] * inv;
#pragma unroll
            for (int i = 0; i < FN; i++) {
                float xv = __ldg(x + n * FN + i);
                v0 += xv * rs[i * 64 + o0];
                v1 += xv * rs[i * 64 + o0 + 1];
            }
            v0 += b1[o0];
            v1 += b1[o0 + 1];
            float s = v0 + v1, sq = v0 * v0 + v1 * v1;
#pragma unroll
            for (int d = 16; d > 0; d >>= 1) {
                s += __shfl_xor_sync(0xffffffffu, s, d);
                sq += __shfl_xor_sync(0xffffffffu, sq, d);
            }
            float m = s * (1.f / 64.f);
            float var = fmaxf(sq * (1.f / 64.f) - m * m, 0.f);
            float rr = rsqrtf(var + 1e-5f);
            float y0 = (v0 - m) * rr * g1[o0] + be1[o0];
            float y1 = (v1 - m) * rr * g1[o0 + 1] + be1[o0 + 1];
            y0 = y0 > 0.f ? y0 : 0.01f * y0;
            y1 = y1 > 0.f ? y1 : 0.01f * y1;
            hs[r][o0] = y0;
            hs[r][o0 + 1] = y1;
            g_h1[n * 64 + o0] = y0;
            g_h1[n * 64 + o0 + 1] = y1;
        }
        __syncthreads();
        // ---- P2 phase ----
        unsigned long long acc[16][2] = {};
#pragma unroll
        for (int i = 0; i < H1C; i++) {
            unsigned long long w0 = wp[i * 16], w1 = wp[i * 16 + 1];
#pragma unroll
            for (int b = 0; b < 16; b++) {
                float hv = hs[which * 16 + b][i];
                unsigned long long hb = pk2(hv, hv);
                acc[b][0] = fma2(w0, hb, acc[b][0]);
                acc[b][1] = fma2(w1, hb, acc[b][1]);
            }
        }
#pragma unroll
        for (int b = 0; b < 16; b++) {
            float a0, a1, a2, a3;
            upk2(acc[b][0], a0, a1);
            upk2(acc[b][1], a2, a3);
            __half2* dst2 =
                (__half2*)(g_P2h + (n0 + which * 16 + b) * 704 + f * 32 + q * 4);
            dst2[0] = __floats2half2_rn(a0, a1);
            dst2[1] = __floats2half2_rn(a2, a3);
        }
        __syncthreads();
    }
}

// ---------------- edge 2: one edge per warp, coop coeff load + shfl ----------------
__global__ void k_edge2(const int* __restrict__ ei, const float* __restrict__ ea) {
    int gt = blockIdx.x * blockDim.x + threadIdx.x;
    int e = gt >> 5, lane = gt & 31;
    if (e >= EE) return;
    int src = ei[e], dst = ei[EE + e];
    const __half* P = g_P2h + src * 704;
    int quad = lane >> 3;
    int col4 = (lane & 7) * 4;
    float myev = (lane < FE) ? __ldg(ea + e * FE + lane) : (lane == 21 ? 1.0f : 0.0f);
    float a0 = 0.f, a1 = 0.f, a2 = 0.f, a3 = 0.f;
#pragma unroll
    for (int qq = 0; qq < 6; qq++) {
        int row = 4 * qq + quad;       // 0..23 (21 bias, 22/23 pad-zero)
        uint2 v = *(const uint2*)(P + row * 32 + col4);
        float c = __shfl_sync(0xffffffffu, myev, row);
        float2 f01 = __half22float2(*(__half2*)&v.x);
        float2 f23 = __half22float2(*(__half2*)&v.y);
        a0 += c * f01.x; a1 += c * f01.y;
        a2 += c * f23.x; a3 += c * f23.y;
    }
#pragma unroll
    for (int d = 8; d <= 16; d <<= 1) {
        a0 += __shfl_xor_sync(0xffffffffu, a0, d);
        a1 += __shfl_xor_sync(0xffffffffu, a1, d);
        a2 += __shfl_xor_sync(0xffffffffu, a2, d);
        a3 += __shfl_xor_sync(0xffffffffu, a3, d);
    }
    float val = (quad == 0) ? a0 : (quad == 1) ? a1 : (quad == 2) ? a2 : a3;
    atomicAdd(g_acc2 + dst * 32 + col4 + quad, val);
}

// ---------------- fused node2 + LSTM input projections ----------------
__global__ void __launch_bounds__(256) k_n2pre(const float* __restrict__ root2,
                                               const float* __restrict__ b2,
                                               const float* __restrict__ g2,
                                               const float* __restrict__ be2,
                                               const float* __restrict__ Wf,
                                               const float* __restrict__ bihf,
                                               const float* __restrict__ bhhf,
                                               const float* __restrict__ Wb,
                                               const float* __restrict__ bihb,
                                               const float* __restrict__ bhhb) {
    __shared__ float rs[H1C * H2C];
    __shared__ float hsm[32][H2C];
    for (int i = threadIdx.x; i < H1C * H2C; i += 256) rs[i] = root2[i];
    __syncthreads();
    int nb = blockIdx.x * 32;
    int w = threadIdx.x >> 5, lane = threadIdx.x & 31;
    // ---- node2 phase: warp per node ----
    for (int r = w; r < 32; r += 8) {
        int n = nb + r;
        float v = 0.f;
        if (lane < 30) {
            int cnt = g_cnt[n];
            v = g_acc2[n * 32 + lane] * (1.f / (float)(cnt > 0 ? cnt : 1));
#pragma unroll
            for (int i = 0; i < H1C; i++) v += g_h1[n * 64 + i] * rs[i * 30 + lane];
            v += b2[lane];
        }
        float s = (lane < 30) ? v : 0.f;
        float sq = (lane < 30) ? v * v : 0.f;
#pragma unroll
        for (int d = 16; d > 0; d >>= 1) {
            s += __shfl_xor_sync(0xffffffffu, s, d);
            sq += __shfl_xor_sync(0xffffffffu, sq, d);
        }
        float m = s * (1.f / 30.f);
        float var = fmaxf(sq * (1.f / 30.f) - m * m, 0.f);
        float rr = rsqrtf(var + 1e-5f);
        if (lane < 30) {
            float y = (v - m) * rr * g2[lane] + be2[lane];
            hsm[r][lane] = y > 0.f ? y : 0.01f * y;
        }
    }
    __syncthreads();
    // ---- pre phase ----
    int g = threadIdx.x;
    float wr[H2C];
#pragma unroll
    for (int k = 0; k < H2C; k++) wr[k] = __ldg(Wf + g * H2C + k);
    float bias = bihf[g] + bhhf[g];
    for (int nn = 0; nn < 32; nn++) {
        float a = bias;
#pragma unroll
        for (int k = 0; k < H2C; k++) a += wr[k] * hsm[nn][k];
        g_pre[(nb + nn) * 256 + g] = a;
    }
#pragma unroll
    for (int k = 0; k < H2C; k++) wr[k] = __ldg(Wb + g * H2C + k);
    bias = bihb[g] + bhhb[g];
    for (int nn = 0; nn < 32; nn++) {
        float a = bias;
#pragma unroll
        for (int k = 0; k < H2C; k++) a += wr[k] * hsm[nn][k];
        g_pre[NN * 256 + (NN - 1 - (nb + nn)) * 256 + g] = a;
    }
}

// ---------------- chunked BiLSTM: 1 barrier/step, warp-local gate combine ----------------
__global__ void __launch_bounds__(256, 2) k_lstm(const float* __restrict__ WhhF,
                                                 const float* __restrict__ WhhB) {
    int chunk = blockIdx.x >> 1;
    int dir = blockIdx.x & 1;
    const float* Whh = dir ? WhhB : WhhF;
    const float* pre = g_pre + (dir ? NN * 256 : 0);
    int tid = threadIdx.x;
    int w = tid >> 5, lane = tid & 31;
    int type = lane >> 3;          // 0=i 1=f 2=g 3=o
    int ci = lane & 7;
    int cell = w * 8 + ci;
    int row = type * 64 + cell;    // PyTorch gate-row order
    unsigned long long wp[32];
#pragma unroll
    for (int k = 0; k < 32; k++)
        wp[k] = pk2(__ldg(Whh + row * 64 + 2 * k), __ldg(Whh + row * 64 + 2 * k + 1));
    __shared__ __align__(16) float sh_h[2][64];
    int tstart = chunk * CLEN;
    int tend = tstart + CLEN;
    if (tend > NN) tend = NN;
    int t0 = tstart - WARM;
    if (t0 < 0) t0 = 0;
    float c = 0.f;
    if (tid < 64) {
        sh_h[0][tid] = 0.f;
        sh_h[1][tid] = 0.f;
    }
    __syncthreads();
    float preR[4];
#pragma unroll
    for (int u2 = 0; u2 < 4; u2++)
        preR[u2] = (t0 + u2 < tend) ? __ldg(pre + (t0 + u2) * 256 + row) : 0.f;
    for (int tb = t0; tb < tend; tb += 4) {
#pragma unroll
        for (int u2 = 0; u2 < 4; u2++) {
            int t = tb + u2;
            if (t < tend) {   // uniform across block
                int rb = u2 & 1;
                float accs = preR[u2];
                int tp = t + 4;
                preR[u2] = (tp < tend) ? __ldg(pre + tp * 256 + row) : 0.f;
                unsigned long long a0 = pk2(accs, 0.f), a1 = 0ull, a2 = 0ull, a3 = 0ull;
                const ulonglong2* hp = (const ulonglong2*)sh_h[rb];
#pragma unroll
                for (int kk = 0; kk < 16; kk++) {
                    ulonglong2 hv = hp[kk];
                    if ((kk & 1) == 0) {
                        a0 = fma2(wp[2 * kk], hv.x, a0);
                        a1 = fma2(wp[2 * kk + 1], hv.y, a1);
                    } else {
                        a2 = fma2(wp[2 * kk], hv.x, a2);
                        a3 = fma2(wp[2 * kk + 1], hv.y, a3);
                    }
                }
                float l0, u0, l1, u1, l2, u2f, l3, u3;
                upk2(a0, l0, u0); upk2(a1, l1, u1);
                upk2(a2, l2, u2f); upk2(a3, l3, u3);
                float xg = ((l0 + l1) + (l2 + l3)) + ((u0 + u1) + (u2f + u3));
                float z = (type == 2) ? xg : 0.5f * xg;
                float th = fast_tanh(z);
                float av = (type == 2) ? th : 0.5f * th + 0.5f;
                float fv = __shfl_sync(0xffffffffu, av, (lane + 8) & 31);
                float gv = __shfl_sync(0xffffffffu, av, (lane + 16) & 31);
                float ov = __shfl_sync(0xffffffffu, av, (lane + 24) & 31);
                if (type == 0) {
                    c = fv * c + av * gv;
                    float hv = ov * fast_tanh(c);
                    sh_h[1 - rb][cell] = hv;
                    if (t >= tstart) {
                        int node = dir ? (NN - 1 - t) : t;
                        g_hcat[node * 128 + dir * 64 + cell] = hv;
                    }
                }
                __syncthreads();
            }
        }
    }
}

// ---------------- final LN + FC ----------------
__global__ void k_final(const float* __restrict__ gl, const float* __restrict__ bl,
                        const float* __restrict__ fcw, const float* __restrict__ fcb,
                        float* __restrict__ out) {
    int n = (blockIdx.x * blockDim.x + threadIdx.x) >> 5;
    int lane = threadIdx.x & 31;
    if (n >= NN) return;
    float4 v = *(const float4*)(g_hcat + n * 128 + lane * 4);
    float s = v.x + v.y + v.z + v.w;
    float sq = v.x * v.x + v.y * v.y + v.z * v.z + v.w * v.w;
#pragma unroll
    for (int d = 16; d > 0; d >>= 1) {
        s += __shfl_xor_sync(0xffffffffu, s, d);
        sq += __shfl_xor_sync(0xffffffffu, sq, d);
    }
    float m = s * (1.f / 128.f);
    float var = fmaxf(sq * (1.f / 128.f) - m * m, 0.f);
    float r = rsqrtf(var + 1e-5f);
    float o0 = 0.f, o1 = 0.f;
    int i0 = lane * 4;
    float vv[4] = {v.x, v.y, v.z, v.w};
#pragma unroll
    for (int q = 0; q < 4; q++) {
        float y = (vv[q] - m) * r * __ldg(gl + i0 + q) + __ldg(bl + i0 + q);
        o0 += y * __ldg(fcw + i0 + q);
        o1 += y * __ldg(fcw + 128 + i0 + q);
    }
#pragma unroll
    for (int d = 16; d > 0; d >>= 1) {
        o0 += __shfl_xor_sync(0xffffffffu, o0, d);
        o1 += __shfl_xor_sync(0xffffffffu, o1, d);
    }
    if (lane == 0) {
        out[n * 2] = o0 + fcb[0];
        out[n * 2 + 1] = o1 + fcb[1];
    }
}

// ---------------- launcher ----------------
extern "C" void kernel_launch(void* const* d_in, const int* in_sizes, int n_in,
                              void* d_out, int out_size) {
    const float* x    = (const float*)d_in[0];
    const int*   ei   = (const int*)d_in[1];
    const float* ea   = (const float*)d_in[2];
    const float* ew1  = (const float*)d_in[3];
    const float* eb1  = (const float*)d_in[4];
    const float* root1= (const float*)d_in[5];
    const float* b1   = (const float*)d_in[6];
    const float* g1   = (const float*)d_in[7];
    const float* be1  = (const float*)d_in[8];
    const float* ew2  = (const float*)d_in[9];
    const float* eb2  = (const float*)d_in[10];
    const float* root2= (const float*)d_in[11];
    const float* b2   = (const float*)d_in[12];
    const float* g2   = (const float*)d_in[13];
    const float* be2  = (const float*)d_in[14];
    const float* Wih_f= (const float*)d_in[15];
    const float* Whh_f= (const float*)d_in[16];
    const float* bih_f= (const float*)d_in[17];
    const float* bhh_f= (const float*)d_in[18];
    const float* Wih_b= (const float*)d_in[19];
    const float* Whh_b= (const float*)d_in[20];
    const float* bih_b= (const float*)d_in[21];
    const float* bhh_b= (const float*)d_in[22];
    const float* gl   = (const float*)d_in[23];
    const float* bl   = (const float*)d_in[24];
    const float* fcw  = (const float*)d_in[25];
    const float* fcb  = (const float*)d_in[26];
    float* out = (float*)d_out;

    static bool attr_done = false;
    if (!attr_done) {
        cudaFuncSetAttribute(k_p1, cudaFuncAttributeMaxDynamicSharedMemorySize,
                             22 * 26 * 64 * 4);
        cudaFuncSetAttribute(k_p2n1, cudaFuncAttributeMaxDynamicSharedMemorySize,
                             22 * 64 * 32 * 4);
        attr_done = true;
    }

    k_init<<<256, 256>>>(ew1, eb1, ew2, eb2);
    k_cnt<<<(EE + 255) / 256, 256>>>(ei);
    k_p1<<<148, 352, 22 * 26 * 64 * 4>>>(x);
    k_edge1<<<(EE * 32 + 255) / 256, 256>>>(ei, ea);
    k_p2n1<<<148, 352, 22 * 64 * 32 * 4>>>(x, root1, b1, g1, be1);
    k_edge2<<<(EE * 32 + 255) / 256, 256>>>(ei, ea);
    k_n2pre<<<NN / 32, 256>>>(root2, b2, g2, be2,
                              Wih_f, bih_f, bhh_f, Wih_b, bih_b, bhh_b);
    k_lstm<<<2 * NCHUNK, 256>>>(Whh_f, Whh_b);
    k_final<<<(NN * 32 + 255) / 256, 256>>>(gl, bl, fcw, fcb, out);
}

// round 16
// speedup vs baseline: 1.0524x; 1.0177x over previous
#include <cuda_runtime.h>
#include <cuda_fp16.h>

#define NN 20000
#define EE 100000
#define FN 26
#define FE 21
#define H1C 64
#define H2C 30
#define NCHUNK 148
#define WARM 16
#define CLEN 136   // 148*136 = 20128 >= 20000, divisible by 4

// ---------------- device scratch ----------------
__device__ float  g_W1t[22 * 26 * 64];        // [f][i][o]  (f=21 -> eb1 row)
__device__ float  g_W2t[22 * 64 * 32];        // [f][i][o pad32]
__device__ __half g_P1h[NN * 1408 + 256];     // fp16 P1, +pad for 4-row uint4 loads
__device__ __half g_P2h[NN * 704 + 128];      // +pad for 8-row uint4 loads
__device__ float  g_acc1[NN * 64];
__device__ float  g_acc2[NN * 32];
__device__ int    g_cnt[NN];                  // dst degree
__device__ float  g_h1[NN * 64];
__device__ float  g_pre[2 * NN * 256];        // [dir][t][gate-row]
__device__ float  g_hcat[NN * 128];

// ---------------- helpers ----------------
__device__ __forceinline__ unsigned long long pk2(float lo, float hi) {
    unsigned long long r;
    asm("mov.b64 %0,{%1,%2};" : "=l"(r) : "f"(lo), "f"(hi));
    return r;
}
__device__ __forceinline__ void upk2(unsigned long long v, float& lo, float& hi) {
    asm("mov.b64 {%0,%1},%2;" : "=f"(lo), "=f"(hi) : "l"(v));
}
__device__ __forceinline__ unsigned long long fma2(unsigned long long a, unsigned long long b,
                                                   unsigned long long c) {
    unsigned long long d;
    asm("fma.rn.f32x2 %0,%1,%2,%3;" : "=l"(d) : "l"(a), "l"(b), "l"(c));
    return d;
}
__device__ __forceinline__ float fast_tanh(float x) {
    return __fdividef(2.f, 1.f + __expf(-2.f * x)) - 1.f;
}

// ---------------- init: zero + weight rearrange ----------------
__global__ void k_init(const float* __restrict__ ew1, const float* __restrict__ eb1,
                       const float* __restrict__ ew2, const float* __restrict__ eb2) {
    int i = blockIdx.x * blockDim.x + threadIdx.x;
    int st = gridDim.x * blockDim.x;
    for (int j = i; j < NN * 64; j += st) g_acc1[j] = 0.f;
    for (int j = i; j < NN * 32; j += st) g_acc2[j] = 0.f;
    for (int j = i; j < NN; j += st) g_cnt[j] = 0;
    for (int idx = i; idx < 22 * 26 * 64; idx += st) {
        int f = idx / 1664, r = idx - f * 1664;
        int ii = r >> 6, o = r & 63;
        g_W1t[idx] = (f < 21) ? ew1[(ii * 64 + o) * 21 + f] : eb1[ii * 64 + o];
    }
    for (int idx = i; idx < 22 * 64 * 32; idx += st) {
        int f = idx / 2048, r = idx - f * 2048;
        int ii = r >> 5, o = r & 31;
        float v = 0.f;
        if (o < 30) v = (f < 21) ? ew2[(ii * 30 + o) * 21 + f] : eb2[ii * 30 + o];
        g_W2t[idx] = v;
    }
}

__global__ void k_cnt(const int* __restrict__ ei) {
    int e = blockIdx.x * blockDim.x + threadIdx.x;
    if (e < EE) atomicAdd(&g_cnt[ei[EE + e]], 1);
}

// ---------------- P1: node contraction layer 1 (smem weights, 16-node batch) ----------------
__global__ void __launch_bounds__(352, 1) k_p1(const float* __restrict__ x) {
    extern __shared__ float sW[];           // 22*26*64 floats = 146.4 KB
    __shared__ float xs[16][FN];
    for (int i = threadIdx.x; i < 22 * 26 * 64; i += 352) sW[i] = g_W1t[i];
    int u = threadIdx.x;                    // 352 = 22 f-rows * 16 quads
    int f = u >> 4, q = u & 15;
    const unsigned long long* wp =
        (const unsigned long long*)sW + ((f * 1664 + q * 4) >> 1);
    __syncthreads();
    for (int n0 = blockIdx.x * 16; n0 < NN; n0 += gridDim.x * 16) {
        for (int idx = u; idx < 16 * FN; idx += 352)
            xs[idx / FN][idx % FN] = x[(n0 + idx / FN) * FN + (idx % FN)];
        __syncthreads();
        unsigned long long acc[16][2] = {};
#pragma unroll
        for (int i = 0; i < FN; i++) {
            unsigned long long w0 = wp[i * 32], w1 = wp[i * 32 + 1];
#pragma unroll
            for (int b = 0; b < 16; b++) {
                float xv = xs[b][i];
                unsigned long long xb = pk2(xv, xv);
                acc[b][0] = fma2(w0, xb, acc[b][0]);
                acc[b][1] = fma2(w1, xb, acc[b][1]);
            }
        }
#pragma unroll
        for (int b = 0; b < 16; b++) {
            float a0, a1, a2, a3;
            upk2(acc[b][0], a0, a1);
            upk2(acc[b][1], a2, a3);
            __half2* dst = (__half2*)(g_P1h + (n0 + b) * 1408 + f * 64 + q * 4);
            dst[0] = __floats2half2_rn(a0, a1);
            dst[1] = __floats2half2_rn(a2, a3);
        }
        __syncthreads();
    }
}

// ---------------- edge 1: one edge per warp, 6x LDG.128 (4 rows/iter) ----------------
__global__ void __launch_bounds__(256) k_edge1(const int* __restrict__ ei,
                                               const float* __restrict__ ea) {
    int gt = blockIdx.x * blockDim.x + threadIdx.x;
    int e = gt >> 5, lane = gt & 31;
    if (e >= EE) return;
    int src = ei[e], dst = ei[EE + e];
    const __half* P = g_P1h + src * 1408;
    int r = lane >> 3;                 // row offset within 4-row group (0..3)
    int cl = lane & 7;                 // col group: 8 cols each
    // lane L: coeff for row L (21 -> 1.0 bias, 22..31 -> 0 pad)
    float myev = (lane < FE) ? __ldg(ea + e * FE + lane) : (lane == 21 ? 1.0f : 0.0f);
    float a[8] = {0.f, 0.f, 0.f, 0.f, 0.f, 0.f, 0.f, 0.f};
#pragma unroll
    for (int p = 0; p < 6; p++) {
        int row = p * 4 + r;           // 0..23 (21 bias, 22/23 zero-coeff)
        uint4 v = *(const uint4*)(P + row * 64 + cl * 8);
        float c = __shfl_sync(0xffffffffu, myev, row);
        float2 f0 = __half22float2(*(__half2*)&v.x);
        float2 f1 = __half22float2(*(__half2*)&v.y);
        float2 f2 = __half22float2(*(__half2*)&v.z);
        float2 f3 = __half22float2(*(__half2*)&v.w);
        a[0] += c * f0.x; a[1] += c * f0.y;
        a[2] += c * f1.x; a[3] += c * f1.y;
        a[4] += c * f2.x; a[5] += c * f2.y;
        a[6] += c * f3.x; a[7] += c * f3.y;
    }
#pragma unroll
    for (int j = 0; j < 8; j++) {
        a[j] += __shfl_xor_sync(0xffffffffu, a[j], 8);
        a[j] += __shfl_xor_sync(0xffffffffu, a[j], 16);
    }
    // lane (r, cl) commits cols cl*8 + r*2, +1
    float v0 = (r == 0) ? a[0] : (r == 1) ? a[2] : (r == 2) ? a[4] : a[6];
    float v1 = (r == 0) ? a[1] : (r == 1) ? a[3] : (r == 2) ? a[5] : a[7];
    float* dp = g_acc1 + dst * 64 + cl * 8 + r * 2;
    atomicAdd(dp, v0);
    atomicAdd(dp + 1, v1);
}

// ---------------- fused node1 + P2 (32-node tiles) ----------------
__global__ void __launch_bounds__(352, 1) k_p2n1(const float* __restrict__ x,
                                                 const float* __restrict__ root1,
                                                 const float* __restrict__ b1,
                                                 const float* __restrict__ g1,
                                                 const float* __restrict__ be1) {
    extern __shared__ float sW[];           // 22*64*32 floats = 180 KB
    __shared__ float rs[FN * 64];
    __shared__ float hs[32][H1C];
    for (int i = threadIdx.x; i < 22 * 64 * 32; i += 352) sW[i] = g_W2t[i];
    for (int i = threadIdx.x; i < FN * 64; i += 352) rs[i] = root1[i];
    int tid = threadIdx.x;
    int wwarp = tid >> 5, lane = tid & 31;
    int which = tid >= 176;
    int u = tid - which * 176;              // 176 = 22 f-rows * 8 quads
    int f = u >> 3, q = u & 7;
    const unsigned long long* wp =
        (const unsigned long long*)sW + ((f * 2048 + q * 4) >> 1);
    __syncthreads();
    for (int n0 = blockIdx.x * 32; n0 < NN; n0 += gridDim.x * 32) {
        // ---- node1 phase: warp per node ----
        for (int r = wwarp; r < 32; r += 11) {
            int n = n0 + r;
            int cnt = g_cnt[n];
            float inv = 1.f / (float)(cnt > 0 ? cnt : 1);
            int o0 = lane * 2;
            float v0 = g_acc1[n * 64 + o0] * inv;
            float v1 = g_acc1[n * 64 + o0 + 1] * inv;
#pragma unroll
            for (int i = 0; i < FN; i++) {
                float xv = __ldg(x + n * FN + i);
                v0 += xv * rs[i * 64 + o0];
                v1 += xv * rs[i * 64 + o0 + 1];
            }
            v0 += b1[o0];
            v1 += b1[o0 + 1];
            float s = v0 + v1, sq = v0 * v0 + v1 * v1;
#pragma unroll
            for (int d = 16; d > 0; d >>= 1) {
                s += __shfl_xor_sync(0xffffffffu, s, d);
                sq += __shfl_xor_sync(0xffffffffu, sq, d);
            }
            float m = s * (1.f / 64.f);
            float var = fmaxf(sq * (1.f / 64.f) - m * m, 0.f);
            float rr = rsqrtf(var + 1e-5f);
            float y0 = (v0 - m) * rr * g1[o0] + be1[o0];
            float y1 = (v1 - m) * rr * g1[o0 + 1] + be1[o0 + 1];
            y0 = y0 > 0.f ? y0 : 0.01f * y0;
            y1 = y1 > 0.f ? y1 : 0.01f * y1;
            hs[r][o0] = y0;
            hs[r][o0 + 1] = y1;
            g_h1[n * 64 + o0] = y0;
            g_h1[n * 64 + o0 + 1] = y1;
        }
        __syncthreads();
        // ---- P2 phase ----
        unsigned long long acc[16][2] = {};
#pragma unroll
        for (int i = 0; i < H1C; i++) {
            unsigned long long w0 = wp[i * 16], w1 = wp[i * 16 + 1];
#pragma unroll
            for (int b = 0; b < 16; b++) {
                float hv = hs[which * 16 + b][i];
                unsigned long long hb = pk2(hv, hv);
                acc[b][0] = fma2(w0, hb, acc[b][0]);
                acc[b][1] = fma2(w1, hb, acc[b][1]);
            }
        }
#pragma unroll
        for (int b = 0; b < 16; b++) {
            float a0, a1, a2, a3;
            upk2(acc[b][0], a0, a1);
            upk2(acc[b][1], a2, a3);
            __half2* dst2 =
                (__half2*)(g_P2h + (n0 + which * 16 + b) * 704 + f * 32 + q * 4);
            dst2[0] = __floats2half2_rn(a0, a1);
            dst2[1] = __floats2half2_rn(a2, a3);
        }
        __syncthreads();
    }
}

// ---------------- edge 2: one edge per warp, 3x LDG.128 (8 rows/iter) ----------------
__global__ void __launch_bounds__(256) k_edge2(const int* __restrict__ ei,
                                               const float* __restrict__ ea) {
    int gt = blockIdx.x * blockDim.x + threadIdx.x;
    int e = gt >> 5, lane = gt & 31;
    if (e >= EE) return;
    int src = ei[e], dst = ei[EE + e];
    const __half* P = g_P2h + src * 704;
    int r = lane >> 2;                 // row offset within 8-row group (0..7)
    int cl = lane & 3;                 // col group: 8 cols each (32 cols total)
    float myev = (lane < FE) ? __ldg(ea + e * FE + lane) : (lane == 21 ? 1.0f : 0.0f);
    float a[8] = {0.f, 0.f, 0.f, 0.f, 0.f, 0.f, 0.f, 0.f};
#pragma unroll
    for (int p = 0; p < 3; p++) {
        int row = p * 8 + r;           // 0..23 (21 bias, 22/23 zero-coeff)
        uint4 v = *(const uint4*)(P + row * 32 + cl * 8);
        float c = __shfl_sync(0xffffffffu, myev, row);
        float2 f0 = __half22float2(*(__half2*)&v.x);
        float2 f1 = __half22float2(*(__half2*)&v.y);
        float2 f2 = __half22float2(*(__half2*)&v.z);
        float2 f3 = __half22float2(*(__half2*)&v.w);
        a[0] += c * f0.x; a[1] += c * f0.y;
        a[2] += c * f1.x; a[3] += c * f1.y;
        a[4] += c * f2.x; a[5] += c * f2.y;
        a[6] += c * f3.x; a[7] += c * f3.y;
    }
#pragma unroll
    for (int j = 0; j < 8; j++) {
        a[j] += __shfl_xor_sync(0xffffffffu, a[j], 4);
        a[j] += __shfl_xor_sync(0xffffffffu, a[j], 8);
        a[j] += __shfl_xor_sync(0xffffffffu, a[j], 16);
    }
    // lane (r, cl) commits col cl*8 + r
    float v = (r == 0) ? a[0] : (r == 1) ? a[1] : (r == 2) ? a[2] : (r == 3) ? a[3]
            : (r == 4) ? a[4] : (r == 5) ? a[5] : (r == 6) ? a[6] : a[7];
    atomicAdd(g_acc2 + dst * 32 + cl * 8 + r, v);
}

// ---------------- fused node2 + LSTM input projections ----------------
__global__ void __launch_bounds__(256) k_n2pre(const float* __restrict__ root2,
                                               const float* __restrict__ b2,
                                               const float* __restrict__ g2,
                                               const float* __restrict__ be2,
                                               const float* __restrict__ Wf,
                                               const float* __restrict__ bihf,
                                               const float* __restrict__ bhhf,
                                               const float* __restrict__ Wb,
                                               const float* __restrict__ bihb,
                                               const float* __restrict__ bhhb) {
    __shared__ float rs[H1C * H2C];
    __shared__ float hsm[32][H2C];
    for (int i = threadIdx.x; i < H1C * H2C; i += 256) rs[i] = root2[i];
    __syncthreads();
    int nb = blockIdx.x * 32;
    int w = threadIdx.x >> 5, lane = threadIdx.x & 31;
    // ---- node2 phase: warp per node ----
    for (int r = w; r < 32; r += 8) {
        int n = nb + r;
        float v = 0.f;
        if (lane < 30) {
            int cnt = g_cnt[n];
            v = g_acc2[n * 32 + lane] * (1.f / (float)(cnt > 0 ? cnt : 1));
#pragma unroll
            for (int i = 0; i < H1C; i++) v += g_h1[n * 64 + i] * rs[i * 30 + lane];
            v += b2[lane];
        }
        float s = (lane < 30) ? v : 0.f;
        float sq = (lane < 30) ? v * v : 0.f;
#pragma unroll
        for (int d = 16; d > 0; d >>= 1) {
            s += __shfl_xor_sync(0xffffffffu, s, d);
            sq += __shfl_xor_sync(0xffffffffu, sq, d);
        }
        float m = s * (1.f / 30.f);
        float var = fmaxf(sq * (1.f / 30.f) - m * m, 0.f);
        float rr = rsqrtf(var + 1e-5f);
        if (lane < 30) {
            float y = (v - m) * rr * g2[lane] + be2[lane];
            hsm[r][lane] = y > 0.f ? y : 0.01f * y;
        }
    }
    __syncthreads();
    // ---- pre phase ----
    int g = threadIdx.x;
    float wr[H2C];
#pragma unroll
    for (int k = 0; k < H2C; k++) wr[k] = __ldg(Wf + g * H2C + k);
    float bias = bihf[g] + bhhf[g];
    for (int nn = 0; nn < 32; nn++) {
        float a = bias;
#pragma unroll
        for (int k = 0; k < H2C; k++) a += wr[k] * hsm[nn][k];
        g_pre[(nb + nn) * 256 + g] = a;
    }
#pragma unroll
    for (int k = 0; k < H2C; k++) wr[k] = __ldg(Wb + g * H2C + k);
    bias = bihb[g] + bhhb[g];
    for (int nn = 0; nn < 32; nn++) {
        float a = bias;
#pragma unroll
        for (int k = 0; k < H2C; k++) a += wr[k] * hsm[nn][k];
        g_pre[NN * 256 + (NN - 1 - (nb + nn)) * 256 + g] = a;
    }
}

// ---------------- chunked BiLSTM: 1 barrier/step, warp-local gate combine ----------------
__global__ void __launch_bounds__(256, 2) k_lstm(const float* __restrict__ WhhF,
                                                 const float* __restrict__ WhhB) {
    int chunk = blockIdx.x >> 1;
    int dir = blockIdx.x & 1;
    const float* Whh = dir ? WhhB : WhhF;
    const float* pre = g_pre + (dir ? NN * 256 : 0);
    int tid = threadIdx.x;
    int w = tid >> 5, lane = tid & 31;
    int type = lane >> 3;          // 0=i 1=f 2=g 3=o
    int ci = lane & 7;
    int cell = w * 8 + ci;
    int row = type * 64 + cell;    // PyTorch gate-row order
    unsigned long long wp[32];
#pragma unroll
    for (int k = 0; k < 32; k++)
        wp[k] = pk2(__ldg(Whh + row * 64 + 2 * k), __ldg(Whh + row * 64 + 2 * k + 1));
    __shared__ __align__(16) float sh_h[2][64];
    int tstart = chunk * CLEN;
    int tend = tstart + CLEN;
    if (tend > NN) tend = NN;
    int t0 = tstart - WARM;
    if (t0 < 0) t0 = 0;
    float c = 0.f;
    if (tid < 64) {
        sh_h[0][tid] = 0.f;
        sh_h[1][tid] = 0.f;
    }
    __syncthreads();
    float preR[4];
#pragma unroll
    for (int u2 = 0; u2 < 4; u2++)
        preR[u2] = (t0 + u2 < tend) ? __ldg(pre + (t0 + u2) * 256 + row) : 0.f;
    for (int tb = t0; tb < tend; tb += 4) {
#pragma unroll
        for (int u2 = 0; u2 < 4; u2++) {
            int t = tb + u2;
            if (t < tend) {   // uniform across block
                int rb = u2 & 1;
                float accs = preR[u2];
                int tp = t + 4;
                preR[u2] = (tp < tend) ? __ldg(pre + tp * 256 + row) : 0.f;
                unsigned long long a0 = pk2(accs, 0.f), a1 = 0ull, a2 = 0ull, a3 = 0ull;
                const ulonglong2* hp = (const ulonglong2*)sh_h[rb];
#pragma unroll
                for (int kk = 0; kk < 16; kk++) {
                    ulonglong2 hv = hp[kk];
                    if ((kk & 1) == 0) {
                        a0 = fma2(wp[2 * kk], hv.x, a0);
                        a1 = fma2(wp[2 * kk + 1], hv.y, a1);
                    } else {
                        a2 = fma2(wp[2 * kk], hv.x, a2);
                        a3 = fma2(wp[2 * kk + 1], hv.y, a3);
                    }
                }
                float l0, u0, l1, u1, l2, u2f, l3, u3;
                upk2(a0, l0, u0); upk2(a1, l1, u1);
                upk2(a2, l2, u2f); upk2(a3, l3, u3);
                float xg = ((l0 + l1) + (l2 + l3)) + ((u0 + u1) + (u2f + u3));
                float z = (type == 2) ? xg : 0.5f * xg;
                float th = fast_tanh(z);
                float av = (type == 2) ? th : 0.5f * th + 0.5f;
                float fv = __shfl_sync(0xffffffffu, av, (lane + 8) & 31);
                float gv = __shfl_sync(0xffffffffu, av, (lane + 16) & 31);
                float ov = __shfl_sync(0xffffffffu, av, (lane + 24) & 31);
                if (type == 0) {
                    c = fv * c + av * gv;
                    float hv = ov * fast_tanh(c);
                    sh_h[1 - rb][cell] = hv;
                    if (t >= tstart) {
                        int node = dir ? (NN - 1 - t) : t;
                        g_hcat[node * 128 + dir * 64 + cell] = hv;
                    }
                }
                __syncthreads();
            }
        }
    }
}

// ---------------- final LN + FC ----------------
__global__ void k_final(const float* __restrict__ gl, const float* __restrict__ bl,
                        const float* __restrict__ fcw, const float* __restrict__ fcb,
                        float* __restrict__ out) {
    int n = (blockIdx.x * blockDim.x + threadIdx.x) >> 5;
    int lane = threadIdx.x & 31;
    if (n >= NN) return;
    float4 v = *(const float4*)(g_hcat + n * 128 + lane * 4);
    float s = v.x + v.y + v.z + v.w;
    float sq = v.x * v.x + v.y * v.y + v.z * v.z + v.w * v.w;
#pragma unroll
    for (int d = 16; d > 0; d >>= 1) {
        s += __shfl_xor_sync(0xffffffffu, s, d);
        sq += __shfl_xor_sync(0xffffffffu, sq, d);
    }
    float m = s * (1.f / 128.f);
    float var = fmaxf(sq * (1.f / 128.f) - m * m, 0.f);
    float r = rsqrtf(var + 1e-5f);
    float o0 = 0.f, o1 = 0.f;
    int i0 = lane * 4;
    float vv[4] = {v.x, v.y, v.z, v.w};
#pragma unroll
    for (int q = 0; q < 4; q++) {
        float y = (vv[q] - m) * r * __ldg(gl + i0 + q) + __ldg(bl + i0 + q);
        o0 += y * __ldg(fcw + i0 + q);
        o1 += y * __ldg(fcw + 128 + i0 + q);
    }
#pragma unroll
    for (int d = 16; d > 0; d >>= 1) {
        o0 += __shfl_xor_sync(0xffffffffu, o0, d);
        o1 += __shfl_xor_sync(0xffffffffu, o1, d);
    }
    if (lane == 0) {
        out[n * 2] = o0 + fcb[0];
        out[n * 2 + 1] = o1 + fcb[1];
    }
}

// ---------------- launcher ----------------
extern "C" void kernel_launch(void* const* d_in, const int* in_sizes, int n_in,
                              void* d_out, int out_size) {
    const float* x    = (const float*)d_in[0];
    const int*   ei   = (const int*)d_in[1];
    const float* ea   = (const float*)d_in[2];
    const float* ew1  = (const float*)d_in[3];
    const float* eb1  = (const float*)d_in[4];
    const float* root1= (const float*)d_in[5];
    const float* b1   = (const float*)d_in[6];
    const float* g1   = (const float*)d_in[7];
    const float* be1  = (const float*)d_in[8];
    const float* ew2  = (const float*)d_in[9];
    const float* eb2  = (const float*)d_in[10];
    const float* root2= (const float*)d_in[11];
    const float* b2   = (const float*)d_in[12];
    const float* g2   = (const float*)d_in[13];
    const float* be2  = (const float*)d_in[14];
    const float* Wih_f= (const float*)d_in[15];
    const float* Whh_f= (const float*)d_in[16];
    const float* bih_f= (const float*)d_in[17];
    const float* bhh_f= (const float*)d_in[18];
    const float* Wih_b= (const float*)d_in[19];
    const float* Whh_b= (const float*)d_in[20];
    const float* bih_b= (const float*)d_in[21];
    const float* bhh_b= (const float*)d_in[22];
    const float* gl   = (const float*)d_in[23];
    const float* bl   = (const float*)d_in[24];
    const float* fcw  = (const float*)d_in[25];
    const float* fcb  = (const float*)d_in[26];
    float* out = (float*)d_out;

    static bool attr_done = false;
    if (!attr_done) {
        cudaFuncSetAttribute(k_p1, cudaFuncAttributeMaxDynamicSharedMemorySize,
                             22 * 26 * 64 * 4);
        cudaFuncSetAttribute(k_p2n1, cudaFuncAttributeMaxDynamicSharedMemorySize,
                             22 * 64 * 32 * 4);
        attr_done = true;
    }

    k_init<<<256, 256>>>(ew1, eb1, ew2, eb2);
    k_cnt<<<(EE + 255) / 256, 256>>>(ei);
    k_p1<<<148, 352, 22 * 26 * 64 * 4>>>(x);
    k_edge1<<<(EE * 32 + 255) / 256, 256>>>(ei, ea);
    k_p2n1<<<148, 352, 22 * 64 * 32 * 4>>>(x, root1, b1, g1, be1);
    k_edge2<<<(EE * 32 + 255) / 256, 256>>>(ei, ea);
    k_n2pre<<<NN / 32, 256>>>(root2, b2, g2, be2,
                              Wih_f, bih_f, bhh_f, Wih_b, bih_b, bhh_b);
    k_lstm<<<2 * NCHUNK, 256>>>(Whh_f, Whh_b);
    k_final<<<(NN * 32 + 255) / 256, 256>>>(gl, bl, fcw, fcb, out);
}